// round 16
// baseline (speedup 1.0000x reference)
#include <cuda_runtime.h>

typedef unsigned long long u64;
typedef unsigned int u32;

#define NTH 128
#define NWARP 4
#define TILE_W 128
#define TILE_H 128
#define IMG 1024
#define STEPS (TILE_H + 10)      // 138 rows staged per CTA
#define NPAIRS (STEPS / 2)       // 69 beats of 2 rows
#define NPIX (32.0f * 1024.0f * 1024.0f)

// smem geometry (u64 units): [warp][pairbuf][row01][plane][col]
#define PLANE 56                 // 448 B; 448 mod 128 == 64 -> paired planes bank-disjoint
#define ROWB  112                // 2 planes
#define PAIRB 224                // 2 rows
#define WARPR 448                // 2 pair buffers

// Normalized 11-tap Gaussian, sigma=1.5
#define W0 0.00102838f
#define W1 0.00759878f
#define W2 0.03600077f
#define W3 0.10936072f
#define W4 0.21300560f
#define W5 0.26601180f

__device__ float g_part[2048];   // one slot per CTA (write-only -> no init kernel)

__device__ __forceinline__ u64 pack2(float lo, float hi) {
    u64 r;
    asm("mov.b64 %0, {%1,%2};" : "=l"(r) : "f"(lo), "f"(hi));
    return r;
}
__device__ __forceinline__ void unpack2(u64 v, float& lo, float& hi) {
    asm("mov.b64 {%0,%1}, %2;" : "=f"(lo), "=f"(hi) : "l"(v));
}
__device__ __forceinline__ u64 ffma2(u64 a, u64 b, u64 c) {
    u64 d;
    asm("fma.rn.f32x2 %0, %1, %2, %3;" : "=l"(d) : "l"(a), "l"(b), "l"(c));
    return d;
}
__device__ __forceinline__ u64 fmul2(u64 a, u64 b) {
    u64 d;
    asm("mul.rn.f32x2 %0, %1, %2;" : "=l"(d) : "l"(a), "l"(b));
    return d;
}
__device__ __forceinline__ u64 fadd2(u64 a, u64 b) {
    u64 d;
    asm("add.rn.f32x2 %0, %1, %2;" : "=l"(d) : "l"(a), "l"(b));
    return d;
}
__device__ __forceinline__ void lds2(u32 addr, u64& a, u64& b) {
    asm volatile("ld.shared.v2.u64 {%0,%1}, [%2];" : "=l"(a), "=l"(b) : "r"(addr));
}

// horizontal 11-tap conv on packed (x,y) pairs for 2 adjacent columns,
// rolling 4-register tap window (taps t[k] for h0, t[k+1] for h1)
__device__ __forceinline__ void hconv(u32 base, const u64* wr, u64& h0, u64& h1) {
    u64 a0, a1, b0, b1;
    lds2(base, a0, a1);            // t0 t1
    lds2(base + 16u, b0, b1);      // t2 t3
    h0 = fmul2(a0, wr[0]);  h1 = fmul2(a1, wr[0]);
    h0 = ffma2(a1, wr[1], h0);  h1 = ffma2(b0, wr[1], h1);
    h0 = ffma2(b0, wr[2], h0);  h1 = ffma2(b1, wr[2], h1);
    lds2(base + 32u, a0, a1);      // t4 t5
    h0 = ffma2(b1, wr[3], h0);  h1 = ffma2(a0, wr[3], h1);
    h0 = ffma2(a0, wr[4], h0);  h1 = ffma2(a1, wr[4], h1);
    lds2(base + 48u, b0, b1);      // t6 t7
    h0 = ffma2(a1, wr[5], h0);  h1 = ffma2(b0, wr[5], h1);
    h0 = ffma2(b0, wr[4], h0);  h1 = ffma2(b1, wr[4], h1);
    lds2(base + 64u, a0, a1);      // t8 t9
    h0 = ffma2(b1, wr[3], h0);  h1 = ffma2(a0, wr[3], h1);
    h0 = ffma2(a0, wr[2], h0);  h1 = ffma2(a1, wr[2], h1);
    lds2(base + 80u, b0, b1);      // t10 t11
    h0 = ffma2(a1, wr[1], h0);  h1 = ffma2(b0, wr[1], h1);
    h0 = ffma2(b0, wr[0], h0);  h1 = ffma2(b1, wr[0], h1);
}

__device__ __forceinline__ float ssim_px(u64 ab, u64 pq) {
    float A, B, Pv, Q;
    unpack2(ab, A, B);
    unpack2(pq, Pv, Q);
    float A2 = A * A, B2 = B * B;
    float cross = 0.5f * (A2 - B2);   // 2*mu1*mu2
    float sums  = 0.5f * (A2 + B2);   // mu1^2 + mu2^2
    float t12   = 0.5f * (Pv - Q);    // 2*conv(i1*i2)
    float tss   = 0.5f * (Pv + Q);    // conv(i1^2+i2^2)
    float num = (cross + 1e-4f) * (t12 - cross + 9e-4f);
    float den = (sums  + 1e-4f) * (tss - sums  + 9e-4f);
    return __fdividef(num, den);
}

__global__ __launch_bounds__(NTH, 5)
void k_ssim(const float* __restrict__ img1, const float* __restrict__ img2) {
    __shared__ __align__(16) u64 raw[NWARP * WARPR];   // 14336 B
    __shared__ float wpart[NWARP];

    u32 sbase;
    asm("{ .reg .u64 t; cvta.to.shared.u64 t, %1; cvt.u32.u64 %0, t; }"
        : "=r"(sbase) : "l"(raw));

    const int tid  = threadIdx.x;
    const int wid  = tid >> 5;
    const int lane = tid & 31;
    const int half = lane & 1;       // 0: (s,d) plane, 1: (s^2,d^2) plane
    const int pr   = lane >> 1;      // col pair within strip

    const int x0 = blockIdx.x * TILE_W + wid * 32;
    const int y0 = blockIdx.y * TILE_H;
    const int z  = blockIdx.z;
    const size_t ofs = (size_t)z * (size_t)(IMG * IMG);
    const float* p1 = img1 + ofs;
    const float* p2 = img2 + ofs;

    const u64 wr[6] = { pack2(W0, W0), pack2(W1, W1), pack2(W2, W2),
                        pack2(W3, W3), pack2(W4, W4), pack2(W5, W5) };
    const int wi[11] = { 0, 1, 2, 3, 4, 5, 4, 3, 2, 1, 0 };

    // staging columns: 42 px (image x = x0 - 5 + idx)
    const int cA = lane;
    const int cB = 32 + lane;
    const bool actB = (lane < 10);
    const int gxA = x0 - 5 + cA;
    const int gxB = x0 - 5 + cB;
    const bool okxA = ((unsigned)gxA < (unsigned)IMG);
    const bool okxB = actB && ((unsigned)gxB < (unsigned)IMG);

    u64* wr0 = raw + wid * WARPR;
    const u32 wbase = sbase + (u32)(wid * WARPR * 8);
    const u32 tapofs = (u32)((half * PLANE + 2 * pr) * 8);

    u64 ring0[11], ring1[11];        // packed (hx,hy) per staged row, 2 cols
    float ssum = 0.0f;

    // prefetch pair 0 (rows 0,1)
    float aA0, bA0, aB0, bB0, aA1, bA1, aB1, bB1;
    {
        int ry = y0 - 5;
        bool ok0 = ((unsigned)ry < (unsigned)IMG);
        bool ok1 = ((unsigned)(ry + 1) < (unsigned)IMG);
        const float* r1 = p1 + (size_t)ry * IMG;
        const float* r2 = p2 + (size_t)ry * IMG;
        aA0 = (ok0 && okxA) ? __ldg(r1 + gxA) : 0.0f;
        bA0 = (ok0 && okxA) ? __ldg(r2 + gxA) : 0.0f;
        aB0 = (ok0 && okxB) ? __ldg(r1 + gxB) : 0.0f;
        bB0 = (ok0 && okxB) ? __ldg(r2 + gxB) : 0.0f;
        aA1 = (ok1 && okxA) ? __ldg(r1 + IMG + gxA) : 0.0f;
        bA1 = (ok1 && okxA) ? __ldg(r2 + IMG + gxA) : 0.0f;
        aB1 = (ok1 && okxB) ? __ldg(r1 + IMG + gxB) : 0.0f;
        bB1 = (ok1 && okxB) ? __ldg(r2 + IMG + gxB) : 0.0f;
    }

    for (int Pb = 0; Pb < NPAIRS; Pb += 11) {
#pragma unroll
        for (int p = 0; p < 11; ++p) {
            const int P = Pb + p;
            if (P < NPAIRS) {               // uniform
                u64* bb = wr0 + (P & 1) * PAIRB;
                // ---- stage rows 2P, 2P+1 from prefetch regs ----
                {
                    float s = aA0 + bA0, d = aA0 - bA0;
                    bb[cA]         = pack2(s, d);
                    bb[PLANE + cA] = pack2(s * s, d * d);
                    s = aA1 + bA1; d = aA1 - bA1;
                    bb[ROWB + cA]         = pack2(s, d);
                    bb[ROWB + PLANE + cA] = pack2(s * s, d * d);
                    if (actB) {
                        s = aB0 + bB0; d = aB0 - bB0;
                        bb[cB]         = pack2(s, d);
                        bb[PLANE + cB] = pack2(s * s, d * d);
                        s = aB1 + bB1; d = aB1 - bB1;
                        bb[ROWB + cB]         = pack2(s, d);
                        bb[ROWB + PLANE + cB] = pack2(s * s, d * d);
                    }
                }
                __syncwarp();
                // ---- prefetch next pair (rows 2P+2, 2P+3) ----
                {
                    int ry = y0 - 5 + 2 * P + 2;
                    bool ok0 = ((unsigned)ry < (unsigned)IMG) && (2 * P + 2 < STEPS);
                    bool ok1 = ((unsigned)(ry + 1) < (unsigned)IMG) && (2 * P + 3 < STEPS);
                    const float* r1 = p1 + (size_t)ry * IMG;
                    const float* r2 = p2 + (size_t)ry * IMG;
                    aA0 = (ok0 && okxA) ? __ldg(r1 + gxA) : 0.0f;
                    bA0 = (ok0 && okxA) ? __ldg(r2 + gxA) : 0.0f;
                    aB0 = (ok0 && okxB) ? __ldg(r1 + gxB) : 0.0f;
                    bB0 = (ok0 && okxB) ? __ldg(r2 + gxB) : 0.0f;
                    aA1 = (ok1 && okxA) ? __ldg(r1 + IMG + gxA) : 0.0f;
                    bA1 = (ok1 && okxA) ? __ldg(r2 + IMG + gxA) : 0.0f;
                    aB1 = (ok1 && okxB) ? __ldg(r1 + IMG + gxB) : 0.0f;
                    bB1 = (ok1 && okxB) ? __ldg(r2 + IMG + gxB) : 0.0f;
                }

                const u32 base0 = wbase + (u32)((P & 1) * PAIRB * 8) + tapofs;
                const u32 base1 = base0 + (u32)(ROWB * 8);

                // ---- both hconvs back-to-back (independent chains, full ILP) ----
                u64 h00, h01, h10, h11;
                hconv(base0, wr, h00, h01);   // row 2P
                hconv(base1, wr, h10, h11);   // row 2P+1

                // store ONLY row 2P now (evicts row 2P-11, no longer needed);
                // row 2P+1 stays in h10/h11 until after vconv0.
                ring0[(2 * p) % 11] = h00;
                ring1[(2 * p) % 11] = h01;

                // ---- vconv + SSIM for output row 2P-10 (rows 2P-10 .. 2P) ----
                // slot (2p+1)%11 still holds row 2P-10 -> exact.
                // split accumulators: chain A = taps 0..5, chain B = taps 6..10
                if (P >= 5) {                 // uniform
                    const int sb = 2 * p + 1;
                    u64 v0a = fmul2(ring0[sb % 11], wr[0]);
                    u64 v1a = fmul2(ring1[sb % 11], wr[0]);
                    u64 v0b = fmul2(ring0[(sb + 6) % 11], wr[4]);
                    u64 v1b = fmul2(ring1[(sb + 6) % 11], wr[4]);
#pragma unroll
                    for (int j = 1; j < 6; ++j) {
                        const int s = (sb + j) % 11;
                        v0a = ffma2(ring0[s], wr[wi[j]], v0a);
                        v1a = ffma2(ring1[s], wr[wi[j]], v1a);
                    }
#pragma unroll
                    for (int j = 7; j < 11; ++j) {
                        const int s = (sb + j) % 11;
                        v0b = ffma2(ring0[s], wr[wi[j]], v0b);
                        v1b = ffma2(ring1[s], wr[wi[j]], v1b);
                    }
                    u64 v0 = fadd2(v0a, v0b);
                    u64 v1 = fadd2(v1a, v1b);
                    u64 q0 = __shfl_xor_sync(0xffffffffu, v0, 1);
                    u64 q1 = __shfl_xor_sync(0xffffffffu, v1, 1);
                    ssum += ssim_px(half ? q1 : v0, half ? v1 : q0);
                }

                // now store row 2P+1 (legitimately evicts row 2P-10)
                ring0[(2 * p + 1) % 11] = h10;
                ring1[(2 * p + 1) % 11] = h11;

                // ---- vconv + SSIM for output row 2P-9 (rows 2P-9 .. 2P+1) ----
                if (P >= 5) {                 // uniform
                    const int sb = 2 * p + 2;
                    u64 v0a = fmul2(ring0[sb % 11], wr[0]);
                    u64 v1a = fmul2(ring1[sb % 11], wr[0]);
                    u64 v0b = fmul2(ring0[(sb + 6) % 11], wr[4]);
                    u64 v1b = fmul2(ring1[(sb + 6) % 11], wr[4]);
#pragma unroll
                    for (int j = 1; j < 6; ++j) {
                        const int s = (sb + j) % 11;
                        v0a = ffma2(ring0[s], wr[wi[j]], v0a);
                        v1a = ffma2(ring1[s], wr[wi[j]], v1a);
                    }
#pragma unroll
                    for (int j = 7; j < 11; ++j) {
                        const int s = (sb + j) % 11;
                        v0b = ffma2(ring0[s], wr[wi[j]], v0b);
                        v1b = ffma2(ring1[s], wr[wi[j]], v1b);
                    }
                    u64 v0 = fadd2(v0a, v0b);
                    u64 v1 = fadd2(v1a, v1b);
                    u64 q0 = __shfl_xor_sync(0xffffffffu, v0, 1);
                    u64 q1 = __shfl_xor_sync(0xffffffffu, v1, 1);
                    ssum += ssim_px(half ? q1 : v0, half ? v1 : q0);
                }
            }
        }
    }

    // reduction: warp -> smem -> one global write per CTA
#pragma unroll
    for (int off = 16; off > 0; off >>= 1)
        ssum += __shfl_xor_sync(0xffffffffu, ssum, off);
    if (lane == 0) wpart[wid] = ssum;
    __syncthreads();
    if (tid == 0) {
        float acc = 0.0f;
#pragma unroll
        for (int w = 0; w < NWARP; ++w) acc += wpart[w];
        g_part[(z * 8 + blockIdx.y) * 8 + blockIdx.x] = acc;
    }
}

__global__ void k_final(float* out) {
    __shared__ float wp[4];
    const int tid = threadIdx.x;    // 128 threads
    float s = 0.0f;
#pragma unroll
    for (int k = 0; k < 16; ++k)
        s += g_part[tid + 128 * k];
#pragma unroll
    for (int off = 16; off > 0; off >>= 1)
        s += __shfl_xor_sync(0xffffffffu, s, off);
    if ((tid & 31) == 0) wp[tid >> 5] = s;
    __syncthreads();
    if (tid == 0)
        out[0] = 1.0f - (wp[0] + wp[1] + wp[2] + wp[3]) * (1.0f / NPIX);
}

extern "C" void kernel_launch(void* const* d_in, const int* in_sizes, int n_in,
                              void* d_out, int out_size) {
    const float* img1 = (const float*)d_in[0];
    const float* img2 = (const float*)d_in[1];
    float* out = (float*)d_out;

    dim3 grid(IMG / TILE_W, IMG / TILE_H, 32);   // 8 x 8 x 32 = 2048 CTAs
    k_ssim<<<grid, NTH>>>(img1, img2);
    k_final<<<1, 128>>>(out);
}

// round 17
// speedup vs baseline: 1.0455x; 1.0455x over previous
#include <cuda_runtime.h>

typedef unsigned long long u64;
typedef unsigned int u32;

#define NTH 128
#define NWARP 4
#define TILE_W 128
#define TILE_H 128
#define IMG 1024
#define STEPS (TILE_H + 10)      // 138 rows staged per CTA
#define NPAIRS (STEPS / 2)       // 69 beats of 2 rows
#define NPIX (32.0f * 1024.0f * 1024.0f)

// smem geometry (u64 units): [warp][pairbuf][row01][plane][col]
#define PLANE 56                 // 448 B; 448 mod 128 == 64 -> paired planes bank-disjoint
#define ROWB  112                // 2 planes
#define PAIRB 224                // 2 rows
#define WARPR 448                // 2 pair buffers

// Normalized 11-tap Gaussian, sigma=1.5
#define W0 0.00102838f
#define W1 0.00759878f
#define W2 0.03600077f
#define W3 0.10936072f
#define W4 0.21300560f
#define W5 0.26601180f

__device__ float g_part[2048];   // one slot per CTA (write-only -> no init kernel)

__device__ __forceinline__ u64 pack2(float lo, float hi) {
    u64 r;
    asm("mov.b64 %0, {%1,%2};" : "=l"(r) : "f"(lo), "f"(hi));
    return r;
}
__device__ __forceinline__ void unpack2(u64 v, float& lo, float& hi) {
    asm("mov.b64 {%0,%1}, %2;" : "=f"(lo), "=f"(hi) : "l"(v));
}
__device__ __forceinline__ u64 ffma2(u64 a, u64 b, u64 c) {
    u64 d;
    asm("fma.rn.f32x2 %0, %1, %2, %3;" : "=l"(d) : "l"(a), "l"(b), "l"(c));
    return d;
}
__device__ __forceinline__ u64 fmul2(u64 a, u64 b) {
    u64 d;
    asm("mul.rn.f32x2 %0, %1, %2;" : "=l"(d) : "l"(a), "l"(b));
    return d;
}
__device__ __forceinline__ u64 fadd2(u64 a, u64 b) {
    u64 d;
    asm("add.rn.f32x2 %0, %1, %2;" : "=l"(d) : "l"(a), "l"(b));
    return d;
}
__device__ __forceinline__ void lds2(u32 addr, u64& a, u64& b) {
    asm volatile("ld.shared.v2.u64 {%0,%1}, [%2];" : "=l"(a), "=l"(b) : "r"(addr));
}

// horizontal 11-tap conv on packed (x,y) pairs for 2 adjacent columns,
// rolling 4-register tap window (taps t[k] for h0, t[k+1] for h1)
__device__ __forceinline__ void hconv(u32 base, const u64* wr, u64& h0, u64& h1) {
    u64 a0, a1, b0, b1;
    lds2(base, a0, a1);            // t0 t1
    lds2(base + 16u, b0, b1);      // t2 t3
    h0 = fmul2(a0, wr[0]);  h1 = fmul2(a1, wr[0]);
    h0 = ffma2(a1, wr[1], h0);  h1 = ffma2(b0, wr[1], h1);
    h0 = ffma2(b0, wr[2], h0);  h1 = ffma2(b1, wr[2], h1);
    lds2(base + 32u, a0, a1);      // t4 t5
    h0 = ffma2(b1, wr[3], h0);  h1 = ffma2(a0, wr[3], h1);
    h0 = ffma2(a0, wr[4], h0);  h1 = ffma2(a1, wr[4], h1);
    lds2(base + 48u, b0, b1);      // t6 t7
    h0 = ffma2(a1, wr[5], h0);  h1 = ffma2(b0, wr[5], h1);
    h0 = ffma2(b0, wr[4], h0);  h1 = ffma2(b1, wr[4], h1);
    lds2(base + 64u, a0, a1);      // t8 t9
    h0 = ffma2(b1, wr[3], h0);  h1 = ffma2(a0, wr[3], h1);
    h0 = ffma2(a0, wr[2], h0);  h1 = ffma2(a1, wr[2], h1);
    lds2(base + 80u, b0, b1);      // t10 t11
    h0 = ffma2(a1, wr[1], h0);  h1 = ffma2(b0, wr[1], h1);
    h0 = ffma2(b0, wr[0], h0);  h1 = ffma2(b1, wr[0], h1);
}

__device__ __forceinline__ float ssim_px(u64 ab, u64 pq) {
    float A, B, Pv, Q;
    unpack2(ab, A, B);
    unpack2(pq, Pv, Q);
    float A2 = A * A, B2 = B * B;
    float cross = 0.5f * (A2 - B2);   // 2*mu1*mu2
    float sums  = 0.5f * (A2 + B2);   // mu1^2 + mu2^2
    float t12   = 0.5f * (Pv - Q);    // 2*conv(i1*i2)
    float tss   = 0.5f * (Pv + Q);    // conv(i1^2+i2^2)
    float num = (cross + 1e-4f) * (t12 - cross + 9e-4f);
    float den = (sums  + 1e-4f) * (tss - sums  + 9e-4f);
    return __fdividef(num, den);
}

__global__ __launch_bounds__(NTH, 5)
void k_ssim(const float* __restrict__ img1, const float* __restrict__ img2) {
    __shared__ __align__(16) u64 raw[NWARP * WARPR];   // 14336 B
    __shared__ float wpart[NWARP];

    u32 sbase;
    asm("{ .reg .u64 t; cvta.to.shared.u64 t, %1; cvt.u32.u64 %0, t; }"
        : "=r"(sbase) : "l"(raw));

    const int tid  = threadIdx.x;
    const int wid  = tid >> 5;
    const int lane = tid & 31;
    const int half = lane & 1;       // 0: (s,d) plane, 1: (s^2,d^2) plane
    const int pr   = lane >> 1;      // col pair within strip

    const int x0 = blockIdx.x * TILE_W + wid * 32;
    const int y0 = blockIdx.y * TILE_H;
    const int z  = blockIdx.z;
    const size_t ofs = (size_t)z * (size_t)(IMG * IMG);
    const float* p1 = img1 + ofs;
    const float* p2 = img2 + ofs;

    const u64 wr[6] = { pack2(W0, W0), pack2(W1, W1), pack2(W2, W2),
                        pack2(W3, W3), pack2(W4, W4), pack2(W5, W5) };

    // staging columns: 42 px (image x = x0 - 5 + idx)
    const int cA = lane;
    const int cB = 32 + lane;
    const bool actB = (lane < 10);
    const int gxA = x0 - 5 + cA;
    const int gxB = x0 - 5 + cB;
    const bool okxA = ((unsigned)gxA < (unsigned)IMG);
    const bool okxB = actB && ((unsigned)gxB < (unsigned)IMG);

    u64* wr0 = raw + wid * WARPR;
    const u32 wbase = sbase + (u32)(wid * WARPR * 8);
    const u32 tapofs = (u32)((half * PLANE + 2 * pr) * 8);

    u64 ring0[11], ring1[11];        // packed (hx,hy) per staged row, 2 cols
    float ssum = 0.0f;

    // prefetch pair 0 (rows 0,1)
    float aA0, bA0, aB0, bB0, aA1, bA1, aB1, bB1;
    {
        int ry = y0 - 5;
        bool ok0 = ((unsigned)ry < (unsigned)IMG);
        bool ok1 = ((unsigned)(ry + 1) < (unsigned)IMG);
        const float* r1 = p1 + (size_t)ry * IMG;
        const float* r2 = p2 + (size_t)ry * IMG;
        aA0 = (ok0 && okxA) ? __ldg(r1 + gxA) : 0.0f;
        bA0 = (ok0 && okxA) ? __ldg(r2 + gxA) : 0.0f;
        aB0 = (ok0 && okxB) ? __ldg(r1 + gxB) : 0.0f;
        bB0 = (ok0 && okxB) ? __ldg(r2 + gxB) : 0.0f;
        aA1 = (ok1 && okxA) ? __ldg(r1 + IMG + gxA) : 0.0f;
        bA1 = (ok1 && okxA) ? __ldg(r2 + IMG + gxA) : 0.0f;
        aB1 = (ok1 && okxB) ? __ldg(r1 + IMG + gxB) : 0.0f;
        bB1 = (ok1 && okxB) ? __ldg(r2 + IMG + gxB) : 0.0f;
    }

    for (int Pb = 0; Pb < NPAIRS; Pb += 11) {
#pragma unroll
        for (int p = 0; p < 11; ++p) {
            const int P = Pb + p;
            if (P < NPAIRS) {               // uniform
                u64* bb = wr0 + (P & 1) * PAIRB;
                // ---- stage rows 2P, 2P+1 from prefetch regs ----
                {
                    float s = aA0 + bA0, d = aA0 - bA0;
                    bb[cA]         = pack2(s, d);
                    bb[PLANE + cA] = pack2(s * s, d * d);
                    s = aA1 + bA1; d = aA1 - bA1;
                    bb[ROWB + cA]         = pack2(s, d);
                    bb[ROWB + PLANE + cA] = pack2(s * s, d * d);
                    if (actB) {
                        s = aB0 + bB0; d = aB0 - bB0;
                        bb[cB]         = pack2(s, d);
                        bb[PLANE + cB] = pack2(s * s, d * d);
                        s = aB1 + bB1; d = aB1 - bB1;
                        bb[ROWB + cB]         = pack2(s, d);
                        bb[ROWB + PLANE + cB] = pack2(s * s, d * d);
                    }
                }
                __syncwarp();
                // ---- prefetch next pair (rows 2P+2, 2P+3) ----
                {
                    int ry = y0 - 5 + 2 * P + 2;
                    bool ok0 = ((unsigned)ry < (unsigned)IMG) && (2 * P + 2 < STEPS);
                    bool ok1 = ((unsigned)(ry + 1) < (unsigned)IMG) && (2 * P + 3 < STEPS);
                    const float* r1 = p1 + (size_t)ry * IMG;
                    const float* r2 = p2 + (size_t)ry * IMG;
                    aA0 = (ok0 && okxA) ? __ldg(r1 + gxA) : 0.0f;
                    bA0 = (ok0 && okxA) ? __ldg(r2 + gxA) : 0.0f;
                    aB0 = (ok0 && okxB) ? __ldg(r1 + gxB) : 0.0f;
                    bB0 = (ok0 && okxB) ? __ldg(r2 + gxB) : 0.0f;
                    aA1 = (ok1 && okxA) ? __ldg(r1 + IMG + gxA) : 0.0f;
                    bA1 = (ok1 && okxA) ? __ldg(r2 + IMG + gxA) : 0.0f;
                    aB1 = (ok1 && okxB) ? __ldg(r1 + IMG + gxB) : 0.0f;
                    bB1 = (ok1 && okxB) ? __ldg(r2 + IMG + gxB) : 0.0f;
                }

                const u32 base0 = wbase + (u32)((P & 1) * PAIRB * 8) + tapofs;
                const u32 base1 = base0 + (u32)(ROWB * 8);

                // ---- both hconvs back-to-back (independent chains, full ILP) ----
                u64 h00, h01, h10, h11;
                hconv(base0, wr, h00, h01);   // row 2P
                hconv(base1, wr, h10, h11);   // row 2P+1

                // store ONLY row 2P now (evicts row 2P-11, no longer needed);
                // row 2P+1 stays in h10/h11 until after vconv0.
                ring0[(2 * p) % 11] = h00;
                ring1[(2 * p) % 11] = h01;

                // ---- vconv + SSIM for output row 2P-10 (rows 2P-10 .. 2P) ----
                // slot (2p+1)%11 still holds row 2P-10 -> exact.
                // symmetric pairing: w[j] == w[10-j] -> 6-deep FMA chain.
                if (P >= 5) {                 // uniform
                    const int sb = 2 * p + 1;
                    u64 v0 = fmul2(fadd2(ring0[sb % 11], ring0[(sb + 10) % 11]), wr[0]);
                    u64 v1 = fmul2(fadd2(ring1[sb % 11], ring1[(sb + 10) % 11]), wr[0]);
                    v0 = ffma2(fadd2(ring0[(sb + 1) % 11], ring0[(sb + 9) % 11]), wr[1], v0);
                    v1 = ffma2(fadd2(ring1[(sb + 1) % 11], ring1[(sb + 9) % 11]), wr[1], v1);
                    v0 = ffma2(fadd2(ring0[(sb + 2) % 11], ring0[(sb + 8) % 11]), wr[2], v0);
                    v1 = ffma2(fadd2(ring1[(sb + 2) % 11], ring1[(sb + 8) % 11]), wr[2], v1);
                    v0 = ffma2(fadd2(ring0[(sb + 3) % 11], ring0[(sb + 7) % 11]), wr[3], v0);
                    v1 = ffma2(fadd2(ring1[(sb + 3) % 11], ring1[(sb + 7) % 11]), wr[3], v1);
                    v0 = ffma2(fadd2(ring0[(sb + 4) % 11], ring0[(sb + 6) % 11]), wr[4], v0);
                    v1 = ffma2(fadd2(ring1[(sb + 4) % 11], ring1[(sb + 6) % 11]), wr[4], v1);
                    v0 = ffma2(ring0[(sb + 5) % 11], wr[5], v0);
                    v1 = ffma2(ring1[(sb + 5) % 11], wr[5], v1);
                    u64 q0 = __shfl_xor_sync(0xffffffffu, v0, 1);
                    u64 q1 = __shfl_xor_sync(0xffffffffu, v1, 1);
                    ssum += ssim_px(half ? q1 : v0, half ? v1 : q0);
                }

                // now store row 2P+1 (legitimately evicts row 2P-10)
                ring0[(2 * p + 1) % 11] = h10;
                ring1[(2 * p + 1) % 11] = h11;

                // ---- vconv + SSIM for output row 2P-9 (rows 2P-9 .. 2P+1) ----
                if (P >= 5) {                 // uniform
                    const int sb = 2 * p + 2;
                    u64 v0 = fmul2(fadd2(ring0[sb % 11], ring0[(sb + 10) % 11]), wr[0]);
                    u64 v1 = fmul2(fadd2(ring1[sb % 11], ring1[(sb + 10) % 11]), wr[0]);
                    v0 = ffma2(fadd2(ring0[(sb + 1) % 11], ring0[(sb + 9) % 11]), wr[1], v0);
                    v1 = ffma2(fadd2(ring1[(sb + 1) % 11], ring1[(sb + 9) % 11]), wr[1], v1);
                    v0 = ffma2(fadd2(ring0[(sb + 2) % 11], ring0[(sb + 8) % 11]), wr[2], v0);
                    v1 = ffma2(fadd2(ring1[(sb + 2) % 11], ring1[(sb + 8) % 11]), wr[2], v1);
                    v0 = ffma2(fadd2(ring0[(sb + 3) % 11], ring0[(sb + 7) % 11]), wr[3], v0);
                    v1 = ffma2(fadd2(ring1[(sb + 3) % 11], ring1[(sb + 7) % 11]), wr[3], v1);
                    v0 = ffma2(fadd2(ring0[(sb + 4) % 11], ring0[(sb + 6) % 11]), wr[4], v0);
                    v1 = ffma2(fadd2(ring1[(sb + 4) % 11], ring1[(sb + 6) % 11]), wr[4], v1);
                    v0 = ffma2(ring0[(sb + 5) % 11], wr[5], v0);
                    v1 = ffma2(ring1[(sb + 5) % 11], wr[5], v1);
                    u64 q0 = __shfl_xor_sync(0xffffffffu, v0, 1);
                    u64 q1 = __shfl_xor_sync(0xffffffffu, v1, 1);
                    ssum += ssim_px(half ? q1 : v0, half ? v1 : q0);
                }
            }
        }
    }

    // reduction: warp -> smem -> one global write per CTA
#pragma unroll
    for (int off = 16; off > 0; off >>= 1)
        ssum += __shfl_xor_sync(0xffffffffu, ssum, off);
    if (lane == 0) wpart[wid] = ssum;
    __syncthreads();
    if (tid == 0) {
        float acc = 0.0f;
#pragma unroll
        for (int w = 0; w < NWARP; ++w) acc += wpart[w];
        g_part[(z * 8 + blockIdx.y) * 8 + blockIdx.x] = acc;
    }
}

__global__ void k_final(float* out) {
    __shared__ float wp[4];
    const int tid = threadIdx.x;    // 128 threads
    float s = 0.0f;
#pragma unroll
    for (int k = 0; k < 16; ++k)
        s += g_part[tid + 128 * k];
#pragma unroll
    for (int off = 16; off > 0; off >>= 1)
        s += __shfl_xor_sync(0xffffffffu, s, off);
    if ((tid & 31) == 0) wp[tid >> 5] = s;
    __syncthreads();
    if (tid == 0)
        out[0] = 1.0f - (wp[0] + wp[1] + wp[2] + wp[3]) * (1.0f / NPIX);
}

extern "C" void kernel_launch(void* const* d_in, const int* in_sizes, int n_in,
                              void* d_out, int out_size) {
    const float* img1 = (const float*)d_in[0];
    const float* img2 = (const float*)d_in[1];
    float* out = (float*)d_out;

    dim3 grid(IMG / TILE_W, IMG / TILE_H, 32);   // 8 x 8 x 32 = 2048 CTAs
    k_ssim<<<grid, NTH>>>(img1, img2);
    k_final<<<1, 128>>>(out);
}